// round 6
// baseline (speedup 1.0000x reference)
#include <cuda_runtime.h>

// Problem constants
#define NH    5
#define LD    10
#define PROJ  50           // NH*LD
#define C_DIM 256
#define B_DIM 32
#define HW    4096
#define M_ROWS (B_DIM * C_DIM)   // 8192
#define BN_EPS 1e-5f
#define KSPLIT 4
#define KSLICE (HW / KSPLIT)     // 1024

// Scratch (device globals: no allocations allowed)
__device__ float g_Pp[3][KSPLIT][M_ROWS * PROJ];  // split-K partials
__device__ float g_P[3][M_ROWS * PROJ];           // reduced projections
__device__ float g_Va[M_ROWS * PROJ];             // attention output
__device__ float g_osum[8][M_ROWS];               // per-(nchunk,row) sum of out
__device__ float g_osq[8][M_ROWS];                // per-(nchunk,row) sum of out^2
__device__ float g_scale[C_DIM];
__device__ float g_shift[C_DIM];

__device__ __forceinline__ unsigned f2tf32(float x) {
    unsigned y;
    asm("cvt.rna.tf32.f32 %0, %1;" : "=r"(y) : "f"(x));
    return y;
}

__device__ __forceinline__ void mma_tf32(float c[4], unsigned a0, unsigned a1,
                                         unsigned a2, unsigned a3,
                                         unsigned b0, unsigned b1) {
    asm volatile(
        "mma.sync.aligned.m16n8k8.row.col.f32.tf32.tf32.f32 "
        "{%0,%1,%2,%3}, {%4,%5,%6,%7}, {%8,%9}, {%0,%1,%2,%3};\n"
        : "+f"(c[0]), "+f"(c[1]), "+f"(c[2]), "+f"(c[3])
        : "r"(a0), "r"(a1), "r"(a2), "r"(a3), "r"(b0), "r"(b1));
}

__device__ __forceinline__ void cp_async16(unsigned smem_dst, const void* gsrc) {
    asm volatile("cp.async.cg.shared.global [%0], [%1], 16;\n"
                 :: "r"(smem_dst), "l"(gsrc));
}
__device__ __forceinline__ void cp_commit() {
    asm volatile("cp.async.commit_group;\n");
}
__device__ __forceinline__ void cp_wait0() {
    asm volatile("cp.async.wait_group 0;\n");
}

// ---------------------------------------------------------------------------
// K1: projection GEMMs, TF32 tensor cores, split-K x4, cp.async double buffer.
// SWAPPED operand roles: mma-A = W (n50 dim as M), mma-B = data rows (as N).
//   D[n50][row] = sum_k W[k][n50] * data[row][k] = P[row][n50]
// A data smem: [2][128][32] raw fp32 bits, XOR swizzle (k ^ 4*(row&7)).
//   B-frag b0 = As[row=g-based][k=t-based] -> bank (kb+t)^(4g): conflict-free.
// W smem: [64][36] tf32, single buffer (rows>=50 zero).
//   A-frag a0 = Wsm[n=g-based][k=t-based] -> bank 4g+t+c: conflict-free.
// Data operand is raw fp32 bits (tf32 truncation) -> zero cvts in mainloop.
// ---------------------------------------------------------------------------
__global__ __launch_bounds__(256) void k_proj_tc(
    const float* __restrict__ q, const float* __restrict__ k,
    const float* __restrict__ v,
    const float* __restrict__ wq, const float* __restrict__ wk,
    const float* __restrict__ wv)
{
    const int z = blockIdx.z;
    const float* __restrict__ A = (z == 0) ? q : (z == 1) ? k : v;
    const float* __restrict__ W = (z == 0) ? wq : (z == 1) ? wk : wv;
    const int slice = blockIdx.y;
    float* __restrict__ P = g_Pp[z][slice];
    const int kbase = slice * KSLICE;

    __shared__ unsigned As[2][128][32];
    __shared__ unsigned Wsm[64][36];

    const int tid  = threadIdx.x;
    const int warp = tid >> 5;
    const int lane = tid & 31;
    const int g = lane >> 2;
    const int t = lane & 3;
    const int wrow = (warp & 3) * 32;   // data-row group (mma-N)
    const int wcol = (warp >> 2) * 32;  // n50 group (mma-M)
    const int m0 = blockIdx.x * 128;

    const unsigned as_base = (unsigned)__cvta_generic_to_shared(&As[0][0][0]);

    // zero W buffer once (rows >= 50 stay zero forever)
    for (int i = tid; i < 64 * 36; i += 256) (&Wsm[0][0])[i] = 0u;
    __syncthreads();

    float acc[2][4][4];
#pragma unroll
    for (int mi = 0; mi < 2; mi++)
#pragma unroll
        for (int ni = 0; ni < 4; ni++)
#pragma unroll
            for (int r = 0; r < 4; r++) acc[mi][ni][r] = 0.f;

    const int wl_n  = tid & 63;      // W load: n index
    const int wl_k0 = (tid >> 6) * 8; // W load: k base (0,8,16,24), j adds 0..7

    auto issue_A = [&](int buf, int k0) {
#pragma unroll
        for (int j = 0; j < 4; j++) {
            int i   = tid + j * 256;
            int row = i >> 3;
            int c4  = (i & 7) * 4;
            int sc  = c4 ^ (4 * (row & 7));
            unsigned dst = as_base + ((buf * 128 + row) * 32 + sc) * 4;
            cp_async16(dst, &A[(size_t)(m0 + row) * HW + k0 + c4]);
        }
        cp_commit();
    };

    // prologue: tile 0
    issue_A(0, kbase);
    if (wl_n < PROJ) {
#pragma unroll
        for (int j = 0; j < 8; j++)
            Wsm[wl_n][wl_k0 + j] = f2tf32(W[(kbase + wl_k0 + j) * PROJ + wl_n]);
    }
    cp_wait0();
    __syncthreads();

    const int NT = KSLICE / 32;   // 32 tiles
    for (int kt = 0; kt < NT; kt++) {
        const int buf = kt & 1;
        const bool haveNext = (kt + 1 < NT);
        float wreg[8];
        if (haveNext) {
            const int k0n = kbase + (kt + 1) * 32;
            issue_A(buf ^ 1, k0n);
            if (wl_n < PROJ) {
#pragma unroll
                for (int j = 0; j < 8; j++)
                    wreg[j] = W[(k0n + wl_k0 + j) * PROJ + wl_n];
            }
        }

#pragma unroll
        for (int ks = 0; ks < 4; ks++) {
            const int kb = ks * 8;
            unsigned a[2][4];
#pragma unroll
            for (int mi = 0; mi < 2; mi++) {
                int n = wcol + mi * 16 + g;
                a[mi][0] = Wsm[n][kb + t];
                a[mi][1] = Wsm[n + 8][kb + t];
                a[mi][2] = Wsm[n][kb + t + 4];
                a[mi][3] = Wsm[n + 8][kb + t + 4];
            }
#pragma unroll
            for (int ni = 0; ni < 4; ni++) {
                int row = wrow + ni * 8 + g;
                unsigned b0 = As[buf][row][(kb + t) ^ (4 * g)];
                unsigned b1 = As[buf][row][(kb + t + 4) ^ (4 * g)];
                mma_tf32(acc[0][ni], a[0][0], a[0][1], a[0][2], a[0][3], b0, b1);
                mma_tf32(acc[1][ni], a[1][0], a[1][1], a[1][2], a[1][3], b0, b1);
            }
        }

        if (haveNext) {
            cp_wait0();
            __syncthreads();     // all warps done reading Wsm + A buf ready
            if (wl_n < PROJ) {
#pragma unroll
                for (int j = 0; j < 8; j++)
                    Wsm[wl_n][wl_k0 + j] = f2tf32(wreg[j]);
            }
            __syncthreads();     // Wsm(kt+1) visible
        }
    }

    // Epilogue: c0=D[g][2t] -> P[row=wrow+ni*8+2t][n50=wcol+mi*16+g]
#pragma unroll
    for (int mi = 0; mi < 2; mi++) {
#pragma unroll
        for (int ni = 0; ni < 4; ni++) {
            int col0 = wcol + mi * 16 + g;
            int col2 = col0 + 8;
            int prow = m0 + wrow + ni * 8 + 2 * t;
            if (col0 < PROJ) {
                P[prow * PROJ + col0]       = acc[mi][ni][0];
                P[(prow + 1) * PROJ + col0] = acc[mi][ni][1];
            }
            if (col2 < PROJ) {
                P[prow * PROJ + col2]       = acc[mi][ni][2];
                P[(prow + 1) * PROJ + col2] = acc[mi][ni][3];
            }
        }
    }
}

// ---------------------------------------------------------------------------
// K1b: reduce split-K partials.
// ---------------------------------------------------------------------------
__global__ __launch_bounds__(256) void k_reduceP()
{
    const int i = blockIdx.x * 256 + threadIdx.x;
    const int per_z = (M_ROWS * PROJ) / 4;
    const int z = i / per_z;
    const int r = i - z * per_z;
    const float4* __restrict__ p = (const float4*)g_Pp;
    float4 a = p[(size_t)(z * KSPLIT + 0) * per_z + r];
    float4 b = p[(size_t)(z * KSPLIT + 1) * per_z + r];
    float4 c = p[(size_t)(z * KSPLIT + 2) * per_z + r];
    float4 d = p[(size_t)(z * KSPLIT + 3) * per_z + r];
    float4 o;
    o.x = (a.x + b.x) + (c.x + d.x);
    o.y = (a.y + b.y) + (c.y + d.y);
    o.z = (a.z + b.z) + (c.z + d.z);
    o.w = (a.w + b.w) + (c.w + d.w);
    ((float4*)g_P)[i] = o;
}

// ---------------------------------------------------------------------------
// K2: attention (tiny). One block per batch, one thread per channel.
// ---------------------------------------------------------------------------
__global__ __launch_bounds__(256) void k_attn()
{
    const int b = blockIdx.x;
    const int c = threadIdx.x;
    const int lane = c & 31;
    const int wid  = c >> 5;

    const float* __restrict__ pq = &g_P[0][(b * C_DIM + c) * PROJ];
    const float* __restrict__ pk = &g_P[1][(b * C_DIM + c) * PROJ];
    const float* __restrict__ pv = &g_P[2][(b * C_DIM + c) * PROJ];

    float s[NH * NH];
#pragma unroll
    for (int i = 0; i < NH; i++)
#pragma unroll
        for (int j = 0; j < NH; j++) {
            float a = 0.f;
#pragma unroll
            for (int l = 0; l < LD; l++)
                a = fmaf(pq[i * LD + l], pk[j * LD + l], a);
            s[i * NH + j] = a;
        }

    __shared__ float sW[8][NH * NH];
    __shared__ float sA[NH * NH];

#pragma unroll
    for (int tt = 0; tt < NH * NH; tt++) {
        float x = s[tt];
#pragma unroll
        for (int off = 16; off > 0; off >>= 1)
            x += __shfl_down_sync(0xffffffffu, x, off);
        if (lane == 0) sW[wid][tt] = x;
    }
    __syncthreads();

    if (c < NH) {
        const int i = c;
        const float inv_scale = rsqrtf((float)(C_DIM * LD));
        float row[NH];
        float mx = -1e30f;
#pragma unroll
        for (int j = 0; j < NH; j++) {
            float a = 0.f;
#pragma unroll
            for (int w = 0; w < 8; w++) a += sW[w][i * NH + j];
            row[j] = a * inv_scale;
            mx = fmaxf(mx, row[j]);
        }
        float sum = 0.f;
#pragma unroll
        for (int j = 0; j < NH; j++) { row[j] = expf(row[j] - mx); sum += row[j]; }
        float inv = 1.f / sum;
#pragma unroll
        for (int j = 0; j < NH; j++) sA[i * NH + j] = row[j] * inv;
    }
    __syncthreads();

    float* __restrict__ va = &g_Va[(b * C_DIM + c) * PROJ];
#pragma unroll
    for (int n = 0; n < NH; n++)
#pragma unroll
        for (int l = 0; l < LD; l++) {
            float a = pv[n * LD + l];
#pragma unroll
            for (int j = 0; j < NH; j++)
                a = fmaf(sA[n * NH + j], pv[j * LD + l], a);
            va[n * LD + l] = a;
        }
}

// ---------------------------------------------------------------------------
// K3: output GEMM + residual + fused BN partial stats.  SWAPPED roles.
// out[8192, 4096] = v + Va[8192,50] @ wfc[50,4096].  K padded 50->56.
// Block: 128 rows x 512-col chunk, looping 8 subtiles of 64 cols.
// VaS filled once/block; Ws refilled per subtile.
// A-frag = Ws[n_out][k] stride 60 (bank 28g+t: conflict-free)
// B-frag = VaS[row][k]  stride 60 (bank 28g+t: conflict-free)
// ---------------------------------------------------------------------------
__global__ __launch_bounds__(256) void k_out_tc(
    const float* __restrict__ v, const float* __restrict__ wfc,
    float* __restrict__ out)
{
    __shared__ unsigned VaS[128][60];
    __shared__ unsigned Ws[64][60];
    __shared__ float Ssum[128][2];
    __shared__ float Ssq[128][2];

    const int tid  = threadIdx.x;
    const int warp = tid >> 5;
    const int lane = tid & 31;
    const int g = lane >> 2;
    const int t = lane & 3;
    const int wrow = (warp & 3) * 32;   // data rows (mma-N)
    const int wcol = (warp >> 2) * 32;  // out cols in subtile (mma-M)
    const int m0    = blockIdx.y * 128;
    const int nbase = blockIdx.x * 512;

    // fill VaS once: 128 rows x 50 (float2 loads), cols 50..55 zero
    for (int i = tid; i < 128 * 25; i += 256) {
        int r  = i / 25;
        int c2 = (i - r * 25) * 2;
        float2 val = *(const float2*)&g_Va[(m0 + r) * PROJ + c2];
        VaS[r][c2]     = f2tf32(val.x);
        VaS[r][c2 + 1] = f2tf32(val.y);
    }
    for (int i = tid; i < 128 * 6; i += 256) {
        int r = i / 6;
        VaS[r][PROJ + (i - r * 6)] = 0u;
    }

    // per-row stats accumulators (rows wrow + ni*8 + 2t + u)
    float rs[4][2], rq[4][2];
#pragma unroll
    for (int ni = 0; ni < 4; ni++) {
        rs[ni][0] = rs[ni][1] = 0.f;
        rq[ni][0] = rq[ni][1] = 0.f;
    }

    for (int s = 0; s < 8; s++) {
        const int n0 = nbase + s * 64;
        __syncthreads();           // prev subtile reads done (also VaS fill, s=0)
        for (int i = tid; i < 64 * 56; i += 256) {
            int n  = i & 63;
            int kk = i >> 6;
            float val = (kk < PROJ) ? wfc[kk * HW + n0 + n] : 0.f;
            Ws[n][kk] = f2tf32(val);
        }
        __syncthreads();

        float acc[2][4][4];
#pragma unroll
        for (int mi = 0; mi < 2; mi++)
#pragma unroll
            for (int ni = 0; ni < 4; ni++)
#pragma unroll
                for (int r = 0; r < 4; r++) acc[mi][ni][r] = 0.f;

#pragma unroll
        for (int ks = 0; ks < 7; ks++) {
            const int kb = ks * 8;
            unsigned a[2][4];
#pragma unroll
            for (int mi = 0; mi < 2; mi++) {
                int n = wcol + mi * 16 + g;
                a[mi][0] = Ws[n][kb + t];
                a[mi][1] = Ws[n + 8][kb + t];
                a[mi][2] = Ws[n][kb + t + 4];
                a[mi][3] = Ws[n + 8][kb + t + 4];
            }
#pragma unroll
            for (int ni = 0; ni < 4; ni++) {
                int row = wrow + ni * 8 + g;
                unsigned b0 = VaS[row][kb + t];
                unsigned b1 = VaS[row][kb + t + 4];
                mma_tf32(acc[0][ni], a[0][0], a[0][1], a[0][2], a[0][3], b0, b1);
                mma_tf32(acc[1][ni], a[1][0], a[1][1], a[1][2], a[1][3], b0, b1);
            }
        }

        // epilogue: c0=D[colg][row2t], c1=row+1, c2=col+8, c3=col+8,row+1
#pragma unroll
        for (int mi = 0; mi < 2; mi++) {
#pragma unroll
            for (int ni = 0; ni < 4; ni++) {
                int col0 = n0 + wcol + mi * 16 + g;
                size_t i00 = (size_t)(m0 + wrow + ni * 8 + 2 * t) * HW + col0;
                size_t i10 = i00 + HW;
                float o00 = v[i00]     + acc[mi][ni][0];
                float o10 = v[i10]     + acc[mi][ni][1];
                float o02 = v[i00 + 8] + acc[mi][ni][2];
                float o12 = v[i10 + 8] + acc[mi][ni][3];
                out[i00]     = o00;
                out[i10]     = o10;
                out[i00 + 8] = o02;
                out[i10 + 8] = o12;
                rs[ni][0] += o00 + o02;
                rs[ni][1] += o10 + o12;
                rq[ni][0] += o00 * o00 + o02 * o02;
                rq[ni][1] += o10 * o10 + o12 * o12;
            }
        }
    }

    // reduce stats over the 8 g-lanes (lane bits 2..4)
#pragma unroll
    for (int ni = 0; ni < 4; ni++)
#pragma unroll
        for (int u = 0; u < 2; u++) {
#pragma unroll
            for (int mask = 4; mask <= 16; mask <<= 1) {
                rs[ni][u] += __shfl_xor_sync(0xffffffffu, rs[ni][u], mask);
                rq[ni][u] += __shfl_xor_sync(0xffffffffu, rq[ni][u], mask);
            }
        }
    if (lane < 4) {   // lane == t, g == 0
#pragma unroll
        for (int ni = 0; ni < 4; ni++)
#pragma unroll
            for (int u = 0; u < 2; u++) {
                int r = wrow + ni * 8 + 2 * lane + u;
                Ssum[r][warp >> 2] = rs[ni][u];
                Ssq[r][warp >> 2]  = rq[ni][u];
            }
    }
    __syncthreads();
    if (tid < 128) {
        g_osum[blockIdx.x][m0 + tid] = Ssum[tid][0] + Ssum[tid][1];
        g_osq[blockIdx.x][m0 + tid]  = Ssq[tid][0] + Ssq[tid][1];
    }
}

// ---------------------------------------------------------------------------
// K4: combine partials -> per-channel scale/shift. 256 blocks x 256 thr.
// ---------------------------------------------------------------------------
__global__ __launch_bounds__(256) void k_bnfinal(
    const float* __restrict__ gamma, const float* __restrict__ beta)
{
    const int c = blockIdx.x;
    const int tid = threadIdx.x;
    const int b  = tid >> 3;   // 0..31
    const int nb = tid & 7;    // 0..7
    float s  = g_osum[nb][b * C_DIM + c];
    float s2 = g_osq[nb][b * C_DIM + c];

    __shared__ float rs[256], rs2[256];
    rs[tid] = s; rs2[tid] = s2;
    __syncthreads();
    for (int off = 128; off > 0; off >>= 1) {
        if (tid < off) { rs[tid] += rs[tid + off]; rs2[tid] += rs2[tid + off]; }
        __syncthreads();
    }
    if (tid == 0) {
        const float inv_n = 1.f / (float)(B_DIM * HW);
        float mean = rs[0] * inv_n;
        float var  = rs2[0] * inv_n - mean * mean;
        float sc = gamma[c] * rsqrtf(var + BN_EPS);
        g_scale[c] = sc;
        g_shift[c] = beta[c] - mean * sc;
    }
}

// ---------------------------------------------------------------------------
// K5: apply BN affine in place.
// ---------------------------------------------------------------------------
__global__ __launch_bounds__(256) void k_apply(float* __restrict__ out)
{
    float4* __restrict__ p = (float4*)out;
    const int idx = blockIdx.x * 256 + threadIdx.x;
#pragma unroll
    for (int tt = 0; tt < 4; tt++) {
        int i = idx + tt * (8192 * 256);
        int c = (i >> 10) & 255;
        float sc = g_scale[c], sh = g_shift[c];
        float4 x = p[i];
        x.x = fmaf(x.x, sc, sh);
        x.y = fmaf(x.y, sc, sh);
        x.z = fmaf(x.z, sc, sh);
        x.w = fmaf(x.w, sc, sh);
        p[i] = x;
    }
}

// ---------------------------------------------------------------------------
extern "C" void kernel_launch(void* const* d_in, const int* in_sizes, int n_in,
                              void* d_out, int out_size)
{
    (void)in_sizes; (void)n_in; (void)out_size;
    const float* q     = (const float*)d_in[0];
    const float* k     = (const float*)d_in[1];
    const float* v     = (const float*)d_in[2];
    const float* wq    = (const float*)d_in[3];
    const float* wk    = (const float*)d_in[4];
    const float* wv    = (const float*)d_in[5];
    const float* wfc   = (const float*)d_in[6];
    const float* gamma = (const float*)d_in[7];
    const float* beta  = (const float*)d_in[8];
    float* out = (float*)d_out;

    k_proj_tc<<<dim3(M_ROWS / 128, KSPLIT, 3), 256>>>(q, k, v, wq, wk, wv);
    k_reduceP<<<(3 * M_ROWS * PROJ / 4) / 256, 256>>>();
    k_attn<<<B_DIM, 256>>>();
    k_out_tc<<<dim3(8, M_ROWS / 128), 256>>>(v, wfc, out);
    k_bnfinal<<<C_DIM, 256>>>(gamma, beta);
    k_apply<<<8192, 256>>>(out);
}

// round 7
// speedup vs baseline: 1.0698x; 1.0698x over previous
#include <cuda_runtime.h>

// Problem constants
#define NH    5
#define LD    10
#define PROJ  50           // NH*LD
#define C_DIM 256
#define B_DIM 32
#define HW    4096
#define M_ROWS (B_DIM * C_DIM)   // 8192
#define BN_EPS 1e-5f
#define KSPLIT 4
#define KSLICE (HW / KSPLIT)     // 1024

// Scratch (device globals: no allocations allowed)
__device__ float g_Pp[3][KSPLIT][M_ROWS * PROJ];  // split-K partials
__device__ float g_P[3][M_ROWS * PROJ];           // reduced projections
__device__ float g_Va[M_ROWS * PROJ];             // attention output
__device__ float g_osum[64][M_ROWS];              // per-(nblk,row) sum of out
__device__ float g_osq[64][M_ROWS];               // per-(nblk,row) sum of out^2
__device__ float g_scale[C_DIM];
__device__ float g_shift[C_DIM];

__device__ __forceinline__ unsigned f2tf32(float x) {
    unsigned y;
    asm("cvt.rna.tf32.f32 %0, %1;" : "=r"(y) : "f"(x));
    return y;
}

__device__ __forceinline__ void mma_tf32(float c[4], unsigned a0, unsigned a1,
                                         unsigned a2, unsigned a3,
                                         unsigned b0, unsigned b1) {
    asm volatile(
        "mma.sync.aligned.m16n8k8.row.col.f32.tf32.tf32.f32 "
        "{%0,%1,%2,%3}, {%4,%5,%6,%7}, {%8,%9}, {%0,%1,%2,%3};\n"
        : "+f"(c[0]), "+f"(c[1]), "+f"(c[2]), "+f"(c[3])
        : "r"(a0), "r"(a1), "r"(a2), "r"(a3), "r"(b0), "r"(b1));
}

__device__ __forceinline__ void cp_async16(unsigned smem_dst, const void* gsrc) {
    asm volatile("cp.async.cg.shared.global [%0], [%1], 16;\n"
                 :: "r"(smem_dst), "l"(gsrc));
}
__device__ __forceinline__ void cp_commit() {
    asm volatile("cp.async.commit_group;\n");
}
__device__ __forceinline__ void cp_wait0() {
    asm volatile("cp.async.wait_group 0;\n");
}

// ---------------------------------------------------------------------------
// K1: projection GEMMs, TF32 tensor cores, split-K x4, cp.async double buffer.
// SWAPPED operand roles: mma-A = W (n50 dim as M), mma-B = data rows (as N).
//   D[n50][row] = sum_k W[k][n50] * data[row][k] = P[row][n50]
// A data smem: [2][128][32] raw fp32 bits, XOR swizzle (k ^ 4*(row&7)).
//   B-frag -> bank (kb+t)^(4g): conflict-free across the warp.
// W smem: [64][36] tf32, single buffer + register prefetch (rows>=50 zero).
//   A-frag -> bank 4g+t+const: conflict-free.
// Data operand raw fp32 bits (tf32 truncation) -> zero cvts in mainloop.
// ---------------------------------------------------------------------------
__global__ __launch_bounds__(256) void k_proj_tc(
    const float* __restrict__ q, const float* __restrict__ k,
    const float* __restrict__ v,
    const float* __restrict__ wq, const float* __restrict__ wk,
    const float* __restrict__ wv)
{
    const int z = blockIdx.z;
    const float* __restrict__ A = (z == 0) ? q : (z == 1) ? k : v;
    const float* __restrict__ W = (z == 0) ? wq : (z == 1) ? wk : wv;
    const int slice = blockIdx.y;
    float* __restrict__ P = g_Pp[z][slice];
    const int kbase = slice * KSLICE;

    __shared__ unsigned As[2][128][32];
    __shared__ unsigned Wsm[64][36];

    const int tid  = threadIdx.x;
    const int warp = tid >> 5;
    const int lane = tid & 31;
    const int g = lane >> 2;
    const int t = lane & 3;
    const int wrow = (warp & 3) * 32;   // data-row group (mma-N)
    const int wcol = (warp >> 2) * 32;  // n50 group (mma-M)
    const int m0 = blockIdx.x * 128;

    const unsigned as_base = (unsigned)__cvta_generic_to_shared(&As[0][0][0]);

    // zero W buffer once (rows >= 50 stay zero forever)
    for (int i = tid; i < 64 * 36; i += 256) (&Wsm[0][0])[i] = 0u;
    __syncthreads();

    float acc[2][4][4];
#pragma unroll
    for (int mi = 0; mi < 2; mi++)
#pragma unroll
        for (int ni = 0; ni < 4; ni++)
#pragma unroll
            for (int r = 0; r < 4; r++) acc[mi][ni][r] = 0.f;

    const int wl_n  = tid & 63;       // W load: n index
    const int wl_k0 = (tid >> 6) * 8; // W load: k base (0,8,16,24)

    auto issue_A = [&](int buf, int k0) {
#pragma unroll
        for (int j = 0; j < 4; j++) {
            int i   = tid + j * 256;
            int row = i >> 3;
            int c4  = (i & 7) * 4;
            int sc  = c4 ^ (4 * (row & 7));
            unsigned dst = as_base + ((buf * 128 + row) * 32 + sc) * 4;
            cp_async16(dst, &A[(size_t)(m0 + row) * HW + k0 + c4]);
        }
        cp_commit();
    };

    // prologue: tile 0
    issue_A(0, kbase);
    if (wl_n < PROJ) {
#pragma unroll
        for (int j = 0; j < 8; j++)
            Wsm[wl_n][wl_k0 + j] = f2tf32(W[(kbase + wl_k0 + j) * PROJ + wl_n]);
    }
    cp_wait0();
    __syncthreads();

    const int NT = KSLICE / 32;   // 32 tiles
    for (int kt = 0; kt < NT; kt++) {
        const int buf = kt & 1;
        const bool haveNext = (kt + 1 < NT);
        float wreg[8];
        if (haveNext) {
            const int k0n = kbase + (kt + 1) * 32;
            issue_A(buf ^ 1, k0n);
            if (wl_n < PROJ) {
#pragma unroll
                for (int j = 0; j < 8; j++)
                    wreg[j] = W[(k0n + wl_k0 + j) * PROJ + wl_n];
            }
        }

#pragma unroll
        for (int ks = 0; ks < 4; ks++) {
            const int kb = ks * 8;
            unsigned a[2][4];
#pragma unroll
            for (int mi = 0; mi < 2; mi++) {
                int n = wcol + mi * 16 + g;
                a[mi][0] = Wsm[n][kb + t];
                a[mi][1] = Wsm[n + 8][kb + t];
                a[mi][2] = Wsm[n][kb + t + 4];
                a[mi][3] = Wsm[n + 8][kb + t + 4];
            }
#pragma unroll
            for (int ni = 0; ni < 4; ni++) {
                int row = wrow + ni * 8 + g;
                unsigned b0 = As[buf][row][(kb + t) ^ (4 * g)];
                unsigned b1 = As[buf][row][(kb + t + 4) ^ (4 * g)];
                mma_tf32(acc[0][ni], a[0][0], a[0][1], a[0][2], a[0][3], b0, b1);
                mma_tf32(acc[1][ni], a[1][0], a[1][1], a[1][2], a[1][3], b0, b1);
            }
        }

        if (haveNext) {
            cp_wait0();
            __syncthreads();     // all warps done reading Wsm + A buf ready
            if (wl_n < PROJ) {
#pragma unroll
                for (int j = 0; j < 8; j++)
                    Wsm[wl_n][wl_k0 + j] = f2tf32(wreg[j]);
            }
            __syncthreads();     // Wsm(kt+1) visible
        }
    }

    // Epilogue: c0=D[g][2t] -> P[row=wrow+ni*8+2t][n50=wcol+mi*16+g]
#pragma unroll
    for (int mi = 0; mi < 2; mi++) {
#pragma unroll
        for (int ni = 0; ni < 4; ni++) {
            int col0 = wcol + mi * 16 + g;
            int col2 = col0 + 8;
            int prow = m0 + wrow + ni * 8 + 2 * t;
            if (col0 < PROJ) {
                P[prow * PROJ + col0]       = acc[mi][ni][0];
                P[(prow + 1) * PROJ + col0] = acc[mi][ni][1];
            }
            if (col2 < PROJ) {
                P[prow * PROJ + col2]       = acc[mi][ni][2];
                P[(prow + 1) * PROJ + col2] = acc[mi][ni][3];
            }
        }
    }
}

// ---------------------------------------------------------------------------
// K1b: reduce split-K partials.
// ---------------------------------------------------------------------------
__global__ __launch_bounds__(256) void k_reduceP()
{
    const int i = blockIdx.x * 256 + threadIdx.x;
    const int per_z = (M_ROWS * PROJ) / 4;
    const int z = i / per_z;
    const int r = i - z * per_z;
    const float4* __restrict__ p = (const float4*)g_Pp;
    float4 a = p[(size_t)(z * KSPLIT + 0) * per_z + r];
    float4 b = p[(size_t)(z * KSPLIT + 1) * per_z + r];
    float4 c = p[(size_t)(z * KSPLIT + 2) * per_z + r];
    float4 d = p[(size_t)(z * KSPLIT + 3) * per_z + r];
    float4 o;
    o.x = (a.x + b.x) + (c.x + d.x);
    o.y = (a.y + b.y) + (c.y + d.y);
    o.z = (a.z + b.z) + (c.z + d.z);
    o.w = (a.w + b.w) + (c.w + d.w);
    ((float4*)g_P)[i] = o;
}

// ---------------------------------------------------------------------------
// K2: attention (tiny). One block per batch, one thread per channel.
// ---------------------------------------------------------------------------
__global__ __launch_bounds__(256) void k_attn()
{
    const int b = blockIdx.x;
    const int c = threadIdx.x;
    const int lane = c & 31;
    const int wid  = c >> 5;

    const float* __restrict__ pq = &g_P[0][(b * C_DIM + c) * PROJ];
    const float* __restrict__ pk = &g_P[1][(b * C_DIM + c) * PROJ];
    const float* __restrict__ pv = &g_P[2][(b * C_DIM + c) * PROJ];

    float s[NH * NH];
#pragma unroll
    for (int i = 0; i < NH; i++)
#pragma unroll
        for (int j = 0; j < NH; j++) {
            float a = 0.f;
#pragma unroll
            for (int l = 0; l < LD; l++)
                a = fmaf(pq[i * LD + l], pk[j * LD + l], a);
            s[i * NH + j] = a;
        }

    __shared__ float sW[8][NH * NH];
    __shared__ float sA[NH * NH];

#pragma unroll
    for (int tt = 0; tt < NH * NH; tt++) {
        float x = s[tt];
#pragma unroll
        for (int off = 16; off > 0; off >>= 1)
            x += __shfl_down_sync(0xffffffffu, x, off);
        if (lane == 0) sW[wid][tt] = x;
    }
    __syncthreads();

    if (c < NH) {
        const int i = c;
        const float inv_scale = rsqrtf((float)(C_DIM * LD));
        float row[NH];
        float mx = -1e30f;
#pragma unroll
        for (int j = 0; j < NH; j++) {
            float a = 0.f;
#pragma unroll
            for (int w = 0; w < 8; w++) a += sW[w][i * NH + j];
            row[j] = a * inv_scale;
            mx = fmaxf(mx, row[j]);
        }
        float sum = 0.f;
#pragma unroll
        for (int j = 0; j < NH; j++) { row[j] = expf(row[j] - mx); sum += row[j]; }
        float inv = 1.f / sum;
#pragma unroll
        for (int j = 0; j < NH; j++) sA[i * NH + j] = row[j] * inv;
    }
    __syncthreads();

    float* __restrict__ va = &g_Va[(b * C_DIM + c) * PROJ];
#pragma unroll
    for (int n = 0; n < NH; n++)
#pragma unroll
        for (int l = 0; l < LD; l++) {
            float a = pv[n * LD + l];
#pragma unroll
            for (int j = 0; j < NH; j++)
                a = fmaf(sA[n * NH + j], pv[j * LD + l], a);
            va[n * LD + l] = a;
        }
}

// ---------------------------------------------------------------------------
// K3: output GEMM + residual + fused BN partial stats.
// out[8192, 4096] = v + Va[8192,50] @ wfc[50,4096].  K padded 50->56.
// One 128x64 tile per block, grid (64 n, 64 m) = 4096 CTAs (Round-5 shape).
// SWAPPED mma roles -> conflict-free frags:
//   A-frag = Ws[n_out][k] stride 60; B-frag = VaS[row][k] stride 60.
// ---------------------------------------------------------------------------
__global__ __launch_bounds__(256) void k_out_tc(
    const float* __restrict__ v, const float* __restrict__ wfc,
    float* __restrict__ out)
{
    __shared__ unsigned VaS[128][60];
    __shared__ unsigned Ws[64][60];
    __shared__ float Ssum[128][2];
    __shared__ float Ssq[128][2];

    const int tid  = threadIdx.x;
    const int warp = tid >> 5;
    const int lane = tid & 31;
    const int g = lane >> 2;
    const int t = lane & 3;
    const int wrow = (warp & 3) * 32;   // data rows (mma-N)
    const int wcol = (warp >> 2) * 32;  // out cols (mma-M)
    const int n0 = blockIdx.x * 64;
    const int m0 = blockIdx.y * 128;

    // fill VaS: 128 rows x 50 (float2 loads), cols 50..55 zero
    for (int i = tid; i < 128 * 25; i += 256) {
        int r  = i / 25;
        int c2 = (i - r * 25) * 2;
        float2 val = *(const float2*)&g_Va[(m0 + r) * PROJ + c2];
        VaS[r][c2]     = f2tf32(val.x);
        VaS[r][c2 + 1] = f2tf32(val.y);
    }
    for (int i = tid; i < 128 * 6; i += 256) {
        int r = i / 6;
        VaS[r][PROJ + (i - r * 6)] = 0u;
    }
    // fill Ws: [n][k], k >= 50 zero
    for (int i = tid; i < 64 * 56; i += 256) {
        int n  = i & 63;
        int kk = i >> 6;
        float val = (kk < PROJ) ? wfc[kk * HW + n0 + n] : 0.f;
        Ws[n][kk] = f2tf32(val);
    }
    __syncthreads();

    float acc[2][4][4];
#pragma unroll
    for (int mi = 0; mi < 2; mi++)
#pragma unroll
        for (int ni = 0; ni < 4; ni++)
#pragma unroll
            for (int r = 0; r < 4; r++) acc[mi][ni][r] = 0.f;

#pragma unroll
    for (int ks = 0; ks < 7; ks++) {
        const int kb = ks * 8;
        unsigned a[2][4];
#pragma unroll
        for (int mi = 0; mi < 2; mi++) {
            int n = wcol + mi * 16 + g;
            a[mi][0] = Ws[n][kb + t];
            a[mi][1] = Ws[n + 8][kb + t];
            a[mi][2] = Ws[n][kb + t + 4];
            a[mi][3] = Ws[n + 8][kb + t + 4];
        }
#pragma unroll
        for (int ni = 0; ni < 4; ni++) {
            int row = wrow + ni * 8 + g;
            unsigned b0 = VaS[row][kb + t];
            unsigned b1 = VaS[row][kb + t + 4];
            mma_tf32(acc[0][ni], a[0][0], a[0][1], a[0][2], a[0][3], b0, b1);
            mma_tf32(acc[1][ni], a[1][0], a[1][1], a[1][2], a[1][3], b0, b1);
        }
    }

    // Epilogue: c0=D[col g][row 2t], c1=row+1, c2=col+8, c3=col+8 row+1.
    float rs[4][2], rq[4][2];
#pragma unroll
    for (int ni = 0; ni < 4; ni++) {
        rs[ni][0] = rs[ni][1] = 0.f;
        rq[ni][0] = rq[ni][1] = 0.f;
    }
#pragma unroll
    for (int mi = 0; mi < 2; mi++) {
#pragma unroll
        for (int ni = 0; ni < 4; ni++) {
            int col0 = n0 + wcol + mi * 16 + g;
            size_t i00 = (size_t)(m0 + wrow + ni * 8 + 2 * t) * HW + col0;
            size_t i10 = i00 + HW;
            float o00 = v[i00]     + acc[mi][ni][0];
            float o10 = v[i10]     + acc[mi][ni][1];
            float o02 = v[i00 + 8] + acc[mi][ni][2];
            float o12 = v[i10 + 8] + acc[mi][ni][3];
            out[i00]     = o00;
            out[i10]     = o10;
            out[i00 + 8] = o02;
            out[i10 + 8] = o12;
            rs[ni][0] += o00 + o02;
            rs[ni][1] += o10 + o12;
            rq[ni][0] += o00 * o00 + o02 * o02;
            rq[ni][1] += o10 * o10 + o12 * o12;
        }
    }

    // reduce stats over the 8 g-lanes (lane bits 2..4)
#pragma unroll
    for (int ni = 0; ni < 4; ni++)
#pragma unroll
        for (int u = 0; u < 2; u++) {
#pragma unroll
            for (int mask = 4; mask <= 16; mask <<= 1) {
                rs[ni][u] += __shfl_xor_sync(0xffffffffu, rs[ni][u], mask);
                rq[ni][u] += __shfl_xor_sync(0xffffffffu, rq[ni][u], mask);
            }
        }
    if (lane < 4) {   // lane == t, g == 0
#pragma unroll
        for (int ni = 0; ni < 4; ni++)
#pragma unroll
            for (int u = 0; u < 2; u++) {
                int r = wrow + ni * 8 + 2 * lane + u;
                Ssum[r][warp >> 2] = rs[ni][u];
                Ssq[r][warp >> 2]  = rq[ni][u];
            }
    }
    __syncthreads();
    if (tid < 128) {
        g_osum[blockIdx.x][m0 + tid] = Ssum[tid][0] + Ssum[tid][1];
        g_osq[blockIdx.x][m0 + tid]  = Ssq[tid][0] + Ssq[tid][1];
    }
}

// ---------------------------------------------------------------------------
// K4: combine partials -> per-channel scale/shift. 256 blocks x 256 thr.
// ---------------------------------------------------------------------------
__global__ __launch_bounds__(256) void k_bnfinal(
    const float* __restrict__ gamma, const float* __restrict__ beta)
{
    const int c = blockIdx.x;
    const int tid = threadIdx.x;
    float s = 0.f, s2 = 0.f;
    for (int i = tid; i < B_DIM * 64; i += 256) {     // 2048 entries
        int b  = i >> 6;
        int nb = i & 63;
        int row = b * C_DIM + c;
        s  += g_osum[nb][row];
        s2 += g_osq[nb][row];
    }
    __shared__ float rs[256], rs2[256];
    rs[tid] = s; rs2[tid] = s2;
    __syncthreads();
    for (int off = 128; off > 0; off >>= 1) {
        if (tid < off) { rs[tid] += rs[tid + off]; rs2[tid] += rs2[tid + off]; }
        __syncthreads();
    }
    if (tid == 0) {
        const float inv_n = 1.f / (float)(B_DIM * HW);
        float mean = rs[0] * inv_n;
        float var  = rs2[0] * inv_n - mean * mean;
        float sc = gamma[c] * rsqrtf(var + BN_EPS);
        g_scale[c] = sc;
        g_shift[c] = beta[c] - mean * sc;
    }
}

// ---------------------------------------------------------------------------
// K5: apply BN affine in place.
// ---------------------------------------------------------------------------
__global__ __launch_bounds__(256) void k_apply(float* __restrict__ out)
{
    float4* __restrict__ p = (float4*)out;
    const int idx = blockIdx.x * 256 + threadIdx.x;
#pragma unroll
    for (int tt = 0; tt < 4; tt++) {
        int i = idx + tt * (8192 * 256);
        int c = (i >> 10) & 255;
        float sc = g_scale[c], sh = g_shift[c];
        float4 x = p[i];
        x.x = fmaf(x.x, sc, sh);
        x.y = fmaf(x.y, sc, sh);
        x.z = fmaf(x.z, sc, sh);
        x.w = fmaf(x.w, sc, sh);
        p[i] = x;
    }
}

// ---------------------------------------------------------------------------
extern "C" void kernel_launch(void* const* d_in, const int* in_sizes, int n_in,
                              void* d_out, int out_size)
{
    (void)in_sizes; (void)n_in; (void)out_size;
    const float* q     = (const float*)d_in[0];
    const float* k     = (const float*)d_in[1];
    const float* v     = (const float*)d_in[2];
    const float* wq    = (const float*)d_in[3];
    const float* wk    = (const float*)d_in[4];
    const float* wv    = (const float*)d_in[5];
    const float* wfc   = (const float*)d_in[6];
    const float* gamma = (const float*)d_in[7];
    const float* beta  = (const float*)d_in[8];
    float* out = (float*)d_out;

    k_proj_tc<<<dim3(M_ROWS / 128, KSPLIT, 3), 256>>>(q, k, v, wq, wk, wv);
    k_reduceP<<<(3 * M_ROWS * PROJ / 4) / 256, 256>>>();
    k_attn<<<B_DIM, 256>>>();
    k_out_tc<<<dim3(HW / 64, M_ROWS / 128), 256>>>(v, wfc, out);
    k_bnfinal<<<C_DIM, 256>>>(gamma, beta);
    k_apply<<<8192, 256>>>(out);
}

// round 8
// speedup vs baseline: 1.0702x; 1.0003x over previous
#include <cuda_runtime.h>

// Problem constants
#define NH    5
#define LD    10
#define PROJ  50           // NH*LD
#define C_DIM 256
#define B_DIM 32
#define HW    4096
#define M_ROWS (B_DIM * C_DIM)   // 8192
#define BN_EPS 1e-5f
#define KSPLIT 4
#define KSLICE (HW / KSPLIT)     // 1024

// Scratch (device globals: no allocations allowed)
__device__ float g_Pp[3][KSPLIT][M_ROWS * PROJ];  // split-K partials
__device__ float g_P[3][M_ROWS * PROJ];           // reduced projections
__device__ float g_Va[M_ROWS * PROJ];             // attention output
__device__ float g_osum[64][M_ROWS];              // per-(nblk,row) sum of out
__device__ float g_osq[64][M_ROWS];               // per-(nblk,row) sum of out^2
__device__ float g_scale[C_DIM];
__device__ float g_shift[C_DIM];

__device__ __forceinline__ unsigned f2tf32(float x) {
    unsigned y;
    asm("cvt.rna.tf32.f32 %0, %1;" : "=r"(y) : "f"(x));
    return y;
}

__device__ __forceinline__ void mma_tf32(float c[4], unsigned a0, unsigned a1,
                                         unsigned a2, unsigned a3,
                                         unsigned b0, unsigned b1) {
    asm volatile(
        "mma.sync.aligned.m16n8k8.row.col.f32.tf32.tf32.f32 "
        "{%0,%1,%2,%3}, {%4,%5,%6,%7}, {%8,%9}, {%0,%1,%2,%3};\n"
        : "+f"(c[0]), "+f"(c[1]), "+f"(c[2]), "+f"(c[3])
        : "r"(a0), "r"(a1), "r"(a2), "r"(a3), "r"(b0), "r"(b1));
}

__device__ __forceinline__ void cp_async16(unsigned smem_dst, const void* gsrc) {
    asm volatile("cp.async.cg.shared.global [%0], [%1], 16;\n"
                 :: "r"(smem_dst), "l"(gsrc));
}
__device__ __forceinline__ void cp_commit() {
    asm volatile("cp.async.commit_group;\n");
}
__device__ __forceinline__ void cp_wait0() {
    asm volatile("cp.async.wait_group 0;\n");
}

// ---------------------------------------------------------------------------
// K1: projection GEMMs, TF32 TC, split-K x4, cp.async + DOUBLE-buffered W.
// Dynamic smem 51200 B:
//   As[2][128][32] raw fp32 bits, XOR swizzle (k ^ 4*(row&7))  -> 32768 B
//   Ws[2][64][36]  tf32 (rows>=50 zero)                        -> 18432 B
// One __syncthreads per K-tile: next W tile STSes into the idle buffer
// while compute reads the current one.
// SWAPPED mma roles: mma-A = W (n50 as M), mma-B = data rows (as N).
// ---------------------------------------------------------------------------
#define AS_ELT(buf, row, col) smd[((buf) * 128 + (row)) * 32 + (col)]
#define WS_ELT(buf, n, k)     smd[8192 + ((buf) * 64 + (n)) * 36 + (k)]
#define PROJ_SMEM_BYTES 51200

__global__ __launch_bounds__(256) void k_proj_tc(
    const float* __restrict__ q, const float* __restrict__ k,
    const float* __restrict__ v,
    const float* __restrict__ wq, const float* __restrict__ wk,
    const float* __restrict__ wv)
{
    extern __shared__ unsigned smd[];

    const int z = blockIdx.z;
    const float* __restrict__ A = (z == 0) ? q : (z == 1) ? k : v;
    const float* __restrict__ W = (z == 0) ? wq : (z == 1) ? wk : wv;
    const int slice = blockIdx.y;
    float* __restrict__ P = g_Pp[z][slice];
    const int kbase = slice * KSLICE;

    const int tid  = threadIdx.x;
    const int warp = tid >> 5;
    const int lane = tid & 31;
    const int g = lane >> 2;
    const int t = lane & 3;
    const int wrow = (warp & 3) * 32;   // data-row group (mma-N)
    const int wcol = (warp >> 2) * 32;  // n50 group (mma-M)
    const int m0 = blockIdx.x * 128;

    const unsigned as_base = (unsigned)__cvta_generic_to_shared(&smd[0]);

    // zero both W buffers (pad rows n>=50 stay zero forever)
    for (int i = tid; i < 2 * 64 * 36; i += 256) smd[8192 + i] = 0u;
    __syncthreads();

    float acc[2][4][4];
#pragma unroll
    for (int mi = 0; mi < 2; mi++)
#pragma unroll
        for (int ni = 0; ni < 4; ni++)
#pragma unroll
            for (int r = 0; r < 4; r++) acc[mi][ni][r] = 0.f;

    const int wl_n  = tid & 63;       // W load: n index
    const int wl_k0 = (tid >> 6) * 8; // W load: k base (0,8,16,24)

    auto issue_A = [&](int buf, int k0) {
#pragma unroll
        for (int j = 0; j < 4; j++) {
            int i   = tid + j * 256;
            int row = i >> 3;
            int c4  = (i & 7) * 4;
            int sc  = c4 ^ (4 * (row & 7));
            unsigned dst = as_base + (((buf * 128 + row) * 32 + sc) << 2);
            cp_async16(dst, &A[(size_t)(m0 + row) * HW + k0 + c4]);
        }
        cp_commit();
    };
    auto load_W = [&](int buf, int k0) {
        if (wl_n < PROJ) {
#pragma unroll
            for (int j = 0; j < 8; j++)
                WS_ELT(buf, wl_n, wl_k0 + j) =
                    f2tf32(W[(k0 + wl_k0 + j) * PROJ + wl_n]);
        }
    };

    // prologue
    issue_A(0, kbase);
    load_W(0, kbase);
    cp_wait0();
    __syncthreads();

    const int NT = KSLICE / 32;   // 32 tiles
    for (int kt = 0; kt < NT; kt++) {
        const int buf = kt & 1;
        const bool haveNext = (kt + 1 < NT);
        if (haveNext) {
            const int k0n = kbase + (kt + 1) * 32;
            issue_A(buf ^ 1, k0n);
            load_W(buf ^ 1, k0n);   // writes idle buffer: no race with compute
        }

#pragma unroll
        for (int ks = 0; ks < 4; ks++) {
            const int kb = ks * 8;
            unsigned a[2][4];
#pragma unroll
            for (int mi = 0; mi < 2; mi++) {
                int n = wcol + mi * 16 + g;
                a[mi][0] = WS_ELT(buf, n, kb + t);
                a[mi][1] = WS_ELT(buf, n + 8, kb + t);
                a[mi][2] = WS_ELT(buf, n, kb + t + 4);
                a[mi][3] = WS_ELT(buf, n + 8, kb + t + 4);
            }
#pragma unroll
            for (int ni = 0; ni < 4; ni++) {
                int row = wrow + ni * 8 + g;
                unsigned b0 = AS_ELT(buf, row, (kb + t) ^ (4 * (row & 7)));
                unsigned b1 = AS_ELT(buf, row, (kb + t + 4) ^ (4 * (row & 7)));
                mma_tf32(acc[0][ni], a[0][0], a[0][1], a[0][2], a[0][3], b0, b1);
                mma_tf32(acc[1][ni], a[1][0], a[1][1], a[1][2], a[1][3], b0, b1);
            }
        }

        if (haveNext) {
            cp_wait0();
            __syncthreads();   // all reads of buf done; next-tile buffers ready
        }
    }

    // Epilogue: c0=D[g][2t] -> P[row=wrow+ni*8+2t][n50=wcol+mi*16+g]
#pragma unroll
    for (int mi = 0; mi < 2; mi++) {
#pragma unroll
        for (int ni = 0; ni < 4; ni++) {
            int col0 = wcol + mi * 16 + g;
            int col2 = col0 + 8;
            int prow = m0 + wrow + ni * 8 + 2 * t;
            if (col0 < PROJ) {
                P[prow * PROJ + col0]       = acc[mi][ni][0];
                P[(prow + 1) * PROJ + col0] = acc[mi][ni][1];
            }
            if (col2 < PROJ) {
                P[prow * PROJ + col2]       = acc[mi][ni][2];
                P[(prow + 1) * PROJ + col2] = acc[mi][ni][3];
            }
        }
    }
}

// ---------------------------------------------------------------------------
// K1b: reduce split-K partials.
// ---------------------------------------------------------------------------
__global__ __launch_bounds__(256) void k_reduceP()
{
    const int i = blockIdx.x * 256 + threadIdx.x;
    const int per_z = (M_ROWS * PROJ) / 4;
    const int z = i / per_z;
    const int r = i - z * per_z;
    const float4* __restrict__ p = (const float4*)g_Pp;
    float4 a = p[(size_t)(z * KSPLIT + 0) * per_z + r];
    float4 b = p[(size_t)(z * KSPLIT + 1) * per_z + r];
    float4 c = p[(size_t)(z * KSPLIT + 2) * per_z + r];
    float4 d = p[(size_t)(z * KSPLIT + 3) * per_z + r];
    float4 o;
    o.x = (a.x + b.x) + (c.x + d.x);
    o.y = (a.y + b.y) + (c.y + d.y);
    o.z = (a.z + b.z) + (c.z + d.z);
    o.w = (a.w + b.w) + (c.w + d.w);
    ((float4*)g_P)[i] = o;
}

// ---------------------------------------------------------------------------
// K2: attention (tiny). One block per batch, one thread per channel.
// ---------------------------------------------------------------------------
__global__ __launch_bounds__(256) void k_attn()
{
    const int b = blockIdx.x;
    const int c = threadIdx.x;
    const int lane = c & 31;
    const int wid  = c >> 5;

    const float* __restrict__ pq = &g_P[0][(b * C_DIM + c) * PROJ];
    const float* __restrict__ pk = &g_P[1][(b * C_DIM + c) * PROJ];
    const float* __restrict__ pv = &g_P[2][(b * C_DIM + c) * PROJ];

    float s[NH * NH];
#pragma unroll
    for (int i = 0; i < NH; i++)
#pragma unroll
        for (int j = 0; j < NH; j++) {
            float a = 0.f;
#pragma unroll
            for (int l = 0; l < LD; l++)
                a = fmaf(pq[i * LD + l], pk[j * LD + l], a);
            s[i * NH + j] = a;
        }

    __shared__ float sW[8][NH * NH];
    __shared__ float sA[NH * NH];

#pragma unroll
    for (int tt = 0; tt < NH * NH; tt++) {
        float x = s[tt];
#pragma unroll
        for (int off = 16; off > 0; off >>= 1)
            x += __shfl_down_sync(0xffffffffu, x, off);
        if (lane == 0) sW[wid][tt] = x;
    }
    __syncthreads();

    if (c < NH) {
        const int i = c;
        const float inv_scale = rsqrtf((float)(C_DIM * LD));
        float row[NH];
        float mx = -1e30f;
#pragma unroll
        for (int j = 0; j < NH; j++) {
            float a = 0.f;
#pragma unroll
            for (int w = 0; w < 8; w++) a += sW[w][i * NH + j];
            row[j] = a * inv_scale;
            mx = fmaxf(mx, row[j]);
        }
        float sum = 0.f;
#pragma unroll
        for (int j = 0; j < NH; j++) { row[j] = expf(row[j] - mx); sum += row[j]; }
        float inv = 1.f / sum;
#pragma unroll
        for (int j = 0; j < NH; j++) sA[i * NH + j] = row[j] * inv;
    }
    __syncthreads();

    float* __restrict__ va = &g_Va[(b * C_DIM + c) * PROJ];
#pragma unroll
    for (int n = 0; n < NH; n++)
#pragma unroll
        for (int l = 0; l < LD; l++) {
            float a = pv[n * LD + l];
#pragma unroll
            for (int j = 0; j < NH; j++)
                a = fmaf(sA[n * NH + j], pv[j * LD + l], a);
            va[n * LD + l] = a;
        }
}

// ---------------------------------------------------------------------------
// K3: output GEMM + residual + fused BN partial stats.
// out[8192, 4096] = v + Va[8192,50] @ wfc[50,4096].  K padded 50->56.
// One 128x64 tile per block, grid (64 n, 64 m) = 4096 CTAs.
// Epilogue STAGES acc through smem (Acc[128][68], banks 8t+g conflict-free),
// then streams float4 v-load / out-store with 16-lane row-sum reduction.
// ---------------------------------------------------------------------------
__global__ __launch_bounds__(256) void k_out_tc(
    const float* __restrict__ v, const float* __restrict__ wfc,
    float* __restrict__ out)
{
    __shared__ __align__(16) unsigned pool[128 * 60 + 64 * 60];  // 46080 B
    unsigned (*VaS)[60] = (unsigned(*)[60])pool;
    unsigned (*Ws)[60]  = (unsigned(*)[60])(pool + 128 * 60);
    float (*Acc)[68]    = (float(*)[68])pool;   // overlays VaS/Ws post-mainloop

    const int tid  = threadIdx.x;
    const int warp = tid >> 5;
    const int lane = tid & 31;
    const int g = lane >> 2;
    const int t = lane & 3;
    const int wrow = (warp & 3) * 32;   // data rows (mma-N)
    const int wcol = (warp >> 2) * 32;  // out cols (mma-M)
    const int n0 = blockIdx.x * 64;
    const int m0 = blockIdx.y * 128;

    // fill VaS: 128 rows x 50 (float2 loads), cols 50..55 zero
    for (int i = tid; i < 128 * 25; i += 256) {
        int r  = i / 25;
        int c2 = (i - r * 25) * 2;
        float2 val = *(const float2*)&g_Va[(m0 + r) * PROJ + c2];
        VaS[r][c2]     = f2tf32(val.x);
        VaS[r][c2 + 1] = f2tf32(val.y);
    }
    for (int i = tid; i < 128 * 6; i += 256) {
        int r = i / 6;
        VaS[r][PROJ + (i - r * 6)] = 0u;
    }
    // fill Ws: [n][k], k >= 50 zero
    for (int i = tid; i < 64 * 56; i += 256) {
        int n  = i & 63;
        int kk = i >> 6;
        float val = (kk < PROJ) ? wfc[kk * HW + n0 + n] : 0.f;
        Ws[n][kk] = f2tf32(val);
    }
    __syncthreads();

    float acc[2][4][4];
#pragma unroll
    for (int mi = 0; mi < 2; mi++)
#pragma unroll
        for (int ni = 0; ni < 4; ni++)
#pragma unroll
            for (int r = 0; r < 4; r++) acc[mi][ni][r] = 0.f;

#pragma unroll
    for (int ks = 0; ks < 7; ks++) {
        const int kb = ks * 8;
        unsigned a[2][4];
#pragma unroll
        for (int mi = 0; mi < 2; mi++) {
            int n = wcol + mi * 16 + g;
            a[mi][0] = Ws[n][kb + t];
            a[mi][1] = Ws[n + 8][kb + t];
            a[mi][2] = Ws[n][kb + t + 4];
            a[mi][3] = Ws[n + 8][kb + t + 4];
        }
#pragma unroll
        for (int ni = 0; ni < 4; ni++) {
            int row = wrow + ni * 8 + g;
            unsigned b0 = VaS[row][kb + t];
            unsigned b1 = VaS[row][kb + t + 4];
            mma_tf32(acc[0][ni], a[0][0], a[0][1], a[0][2], a[0][3], b0, b1);
            mma_tf32(acc[1][ni], a[1][0], a[1][1], a[1][2], a[1][3], b0, b1);
        }
    }

    // stage accumulators into smem (overlays VaS/Ws - mainloop reads are done)
    __syncthreads();
#pragma unroll
    for (int mi = 0; mi < 2; mi++) {
#pragma unroll
        for (int ni = 0; ni < 4; ni++) {
            int row = wrow + ni * 8 + 2 * t;
            int col = wcol + mi * 16 + g;
            Acc[row][col]         = acc[mi][ni][0];
            Acc[row + 1][col]     = acc[mi][ni][1];
            Acc[row][col + 8]     = acc[mi][ni][2];
            Acc[row + 1][col + 8] = acc[mi][ni][3];
        }
    }
    __syncthreads();

    // streamed epilogue: 8 x float4 per thread, full row per 16-lane group
#pragma unroll
    for (int it = 0; it < 8; it++) {
        int f   = tid + it * 256;
        int row = f >> 4;
        int c4  = (f & 15) * 4;
        float4 a = *(float4*)&Acc[row][c4];
        size_t gi = (size_t)(m0 + row) * HW + n0 + c4;
        float4 vv = *(const float4*)&v[gi];
        float4 o;
        o.x = vv.x + a.x;
        o.y = vv.y + a.y;
        o.z = vv.z + a.z;
        o.w = vv.w + a.w;
        *(float4*)&out[gi] = o;
        float s = (o.x + o.y) + (o.z + o.w);
        float qq = (o.x * o.x + o.y * o.y) + (o.z * o.z + o.w * o.w);
#pragma unroll
        for (int msk = 1; msk <= 8; msk <<= 1) {
            s  += __shfl_xor_sync(0xffffffffu, s, msk);
            qq += __shfl_xor_sync(0xffffffffu, qq, msk);
        }
        if ((lane & 15) == 0) {
            g_osum[blockIdx.x][m0 + row] = s;
            g_osq[blockIdx.x][m0 + row]  = qq;
        }
    }
}

// ---------------------------------------------------------------------------
// K4: combine partials -> per-channel scale/shift. 256 blocks x 256 thr.
// ---------------------------------------------------------------------------
__global__ __launch_bounds__(256) void k_bnfinal(
    const float* __restrict__ gamma, const float* __restrict__ beta)
{
    const int c = blockIdx.x;
    const int tid = threadIdx.x;
    float s = 0.f, s2 = 0.f;
    for (int i = tid; i < B_DIM * 64; i += 256) {     // 2048 entries
        int b  = i >> 6;
        int nb = i & 63;
        int row = b * C_DIM + c;
        s  += g_osum[nb][row];
        s2 += g_osq[nb][row];
    }
    __shared__ float rs[256], rs2[256];
    rs[tid] = s; rs2[tid] = s2;
    __syncthreads();
    for (int off = 128; off > 0; off >>= 1) {
        if (tid < off) { rs[tid] += rs[tid + off]; rs2[tid] += rs2[tid + off]; }
        __syncthreads();
    }
    if (tid == 0) {
        const float inv_n = 1.f / (float)(B_DIM * HW);
        float mean = rs[0] * inv_n;
        float var  = rs2[0] * inv_n - mean * mean;
        float sc = gamma[c] * rsqrtf(var + BN_EPS);
        g_scale[c] = sc;
        g_shift[c] = beta[c] - mean * sc;
    }
}

// ---------------------------------------------------------------------------
// K5: apply BN affine in place.
// ---------------------------------------------------------------------------
__global__ __launch_bounds__(256) void k_apply(float* __restrict__ out)
{
    float4* __restrict__ p = (float4*)out;
    const int idx = blockIdx.x * 256 + threadIdx.x;
#pragma unroll
    for (int tt = 0; tt < 4; tt++) {
        int i = idx + tt * (8192 * 256);
        int c = (i >> 10) & 255;
        float sc = g_scale[c], sh = g_shift[c];
        float4 x = p[i];
        x.x = fmaf(x.x, sc, sh);
        x.y = fmaf(x.y, sc, sh);
        x.z = fmaf(x.z, sc, sh);
        x.w = fmaf(x.w, sc, sh);
        p[i] = x;
    }
}

// ---------------------------------------------------------------------------
extern "C" void kernel_launch(void* const* d_in, const int* in_sizes, int n_in,
                              void* d_out, int out_size)
{
    (void)in_sizes; (void)n_in; (void)out_size;
    const float* q     = (const float*)d_in[0];
    const float* k     = (const float*)d_in[1];
    const float* v     = (const float*)d_in[2];
    const float* wq    = (const float*)d_in[3];
    const float* wk    = (const float*)d_in[4];
    const float* wv    = (const float*)d_in[5];
    const float* wfc   = (const float*)d_in[6];
    const float* gamma = (const float*)d_in[7];
    const float* beta  = (const float*)d_in[8];
    float* out = (float*)d_out;

    cudaFuncSetAttribute(k_proj_tc,
                         cudaFuncAttributeMaxDynamicSharedMemorySize,
                         PROJ_SMEM_BYTES);

    k_proj_tc<<<dim3(M_ROWS / 128, KSPLIT, 3), 256, PROJ_SMEM_BYTES>>>(
        q, k, v, wq, wk, wv);
    k_reduceP<<<(3 * M_ROWS * PROJ / 4) / 256, 256>>>();
    k_attn<<<B_DIM, 256>>>();
    k_out_tc<<<dim3(HW / 64, M_ROWS / 128), 256>>>(v, wfc, out);
    k_bnfinal<<<C_DIM, 256>>>(gamma, beta);
    k_apply<<<8192, 256>>>(out);
}